// round 1
// baseline (speedup 1.0000x reference)
#include <cuda_runtime.h>
#include <cuda_bf16.h>
#include <cstdint>

// Problem constants (fixed by the dataset)
#define MAXN 100000
#define MAXE 1600000
#define C 128
#define EPS_BN 1e-5f

// ---------------- persistent device scratch (no allocs allowed) ----------------
__device__ int   g_cnt[MAXN];
__device__ int   g_off[MAXN + 1];
__device__ int   g_cur[MAXN];
__device__ int   g_csr[MAXE];
__device__ float g_dinv[MAXN];
__device__ int   g_bsum[256];
__device__ float g_h[(size_t)MAXN * C];   // GEMM output buffer
__device__ float g_y[(size_t)MAXN * C];   // SpMM output buffer
__device__ float g_z[(size_t)MAXN * 2];   // layer-3 projected features
__device__ float g_aff[2 * 2 * C];        // [layer][scale|shift][C]

// ---------------- preprocessing ----------------
__global__ void k_zero_cnt(int n) {
    int i = blockIdx.x * blockDim.x + threadIdx.x;
    if (i < n) g_cnt[i] = 0;
}

__global__ void k_hist(const int* __restrict__ dst, int e) {
    int i = blockIdx.x * blockDim.x + threadIdx.x;
    if (i < e) atomicAdd(&g_cnt[dst[i]], 1);
}

// block-level exclusive scan, 1024 elems/block
__global__ void k_scan1(int n) {
    __shared__ int sh[1024];
    int i = blockIdx.x * 1024 + threadIdx.x;
    int v = (i < n) ? g_cnt[i] : 0;
    sh[threadIdx.x] = v;
    __syncthreads();
    for (int d = 1; d < 1024; d <<= 1) {
        int t = (threadIdx.x >= (unsigned)d) ? sh[threadIdx.x - d] : 0;
        __syncthreads();
        sh[threadIdx.x] += t;
        __syncthreads();
    }
    if (i < n) g_off[i] = sh[threadIdx.x] - v;     // exclusive
    if (threadIdx.x == 1023) g_bsum[blockIdx.x] = sh[1023];
}

// scan of block sums (nb <= 128)
__global__ void k_scan2(int nb) {
    __shared__ int sh[128];
    int t = threadIdx.x;
    int v = (t < nb) ? g_bsum[t] : 0;
    sh[t] = v;
    __syncthreads();
    for (int d = 1; d < 128; d <<= 1) {
        int u = (t >= d) ? sh[t - d] : 0;
        __syncthreads();
        sh[t] += u;
        __syncthreads();
    }
    if (t < nb) g_bsum[t] = sh[t] - v;             // exclusive
}

__global__ void k_scan3(int n, int e) {
    int i = blockIdx.x * blockDim.x + threadIdx.x;
    if (i < n) {
        int o = g_off[i] + g_bsum[i >> 10];
        g_off[i] = o;
        g_cur[i] = o;
        g_dinv[i] = rsqrtf((float)(g_cnt[i] + 1));  // +1 self loop
    }
    if (i == 0) g_off[n] = e;
}

__global__ void k_fill(const int* __restrict__ src, const int* __restrict__ dst, int e) {
    int i = blockIdx.x * blockDim.x + threadIdx.x;
    if (i < e) {
        int p = atomicAdd(&g_cur[dst[i]], 1);
        g_csr[p] = src[i];
    }
}

// fold bias + BN(eval) into per-channel scale/shift
__global__ void k_affine(const float* __restrict__ b, const float* __restrict__ g,
                         const float* __restrict__ be, const float* __restrict__ rm,
                         const float* __restrict__ rv, int layer) {
    int c = threadIdx.x;
    if (c < C) {
        float s = g[c] * rsqrtf(rv[c] + EPS_BN);
        g_aff[layer * 2 * C + c] = s;                       // scale
        g_aff[layer * 2 * C + C + c] = (b[c] - rm[c]) * s + be[c];  // shift
    }
}

// ---------------- dense GEMM: O[n x 128] = A[n x 128] @ W[128 x 128] ----------------
// Block tile 64x128, 256 threads, thread tile 8x4. Output -> g_h.
__global__ void k_gemm128(const float* __restrict__ Aext, int useExt,
                          const float* __restrict__ W, int n) {
    __shared__ float xs[64][16];
    __shared__ float ws[16][128];
    const float* A = useExt ? Aext : g_y;
    int tid = threadIdx.x;
    int tc = tid & 31;          // col group (4 cols)
    int tr = tid >> 5;          // row group (8 rows)
    int bm0 = blockIdx.x * 64;

    float4 acc[8];
#pragma unroll
    for (int i = 0; i < 8; i++) acc[i] = make_float4(0.f, 0.f, 0.f, 0.f);

    int xrow = tid >> 2;        // 0..63
    int xk = (tid & 3) * 4;     // 0,4,8,12

    for (int k0 = 0; k0 < 128; k0 += 16) {
        float4 xv4 = make_float4(0.f, 0.f, 0.f, 0.f);
        if (bm0 + xrow < n)
            xv4 = *(const float4*)&A[(size_t)(bm0 + xrow) * C + k0 + xk];
        *(float4*)&xs[xrow][xk] = xv4;
#pragma unroll
        for (int q = 0; q < 2; q++) {
            int lin = tid * 2 + q;          // 0..511 (float4 index)
            int wr = lin >> 5;              // 0..15
            int wc = (lin & 31) * 4;        // 0..124
            *(float4*)&ws[wr][wc] = *(const float4*)&W[(size_t)(k0 + wr) * C + wc];
        }
        __syncthreads();
#pragma unroll
        for (int kk = 0; kk < 16; kk++) {
            float4 wv = *(const float4*)&ws[kk][tc * 4];
#pragma unroll
            for (int i = 0; i < 8; i++) {
                float xv = xs[tr * 8 + i][kk];
                acc[i].x += xv * wv.x;
                acc[i].y += xv * wv.y;
                acc[i].z += xv * wv.z;
                acc[i].w += xv * wv.w;
            }
        }
        __syncthreads();
    }
#pragma unroll
    for (int i = 0; i < 8; i++) {
        int r = bm0 + tr * 8 + i;
        if (r < n) *(float4*)&g_h[(size_t)r * C + tc * 4] = acc[i];
    }
}

// ---------------- SpMM: one warp per dst row, 128 channels in float4 regs ----------------
// reads g_h, writes g_y. Epilogue: y = relu(acc*scale + shift)
__global__ void k_spmm(int layer, int n) {
    int w = (blockIdx.x * blockDim.x + threadIdx.x) >> 5;
    if (w >= n) return;
    int lane = threadIdx.x & 31;
    float di = g_dinv[w];

    // self loop: weight dinv^2
    float4 hv = *(const float4*)&g_h[(size_t)w * C + lane * 4];
    float sw = di * di;
    float4 acc = make_float4(sw * hv.x, sw * hv.y, sw * hv.z, sw * hv.w);

    int s = g_off[w], e = g_off[w + 1];
    int j = s;
    for (; j + 1 < e; j += 2) {
        int s0 = g_csr[j], s1 = g_csr[j + 1];
        float w0 = di * g_dinv[s0];
        float w1 = di * g_dinv[s1];
        float4 v0 = *(const float4*)&g_h[(size_t)s0 * C + lane * 4];
        float4 v1 = *(const float4*)&g_h[(size_t)s1 * C + lane * 4];
        acc.x += w0 * v0.x + w1 * v1.x;
        acc.y += w0 * v0.y + w1 * v1.y;
        acc.z += w0 * v0.z + w1 * v1.z;
        acc.w += w0 * v0.w + w1 * v1.w;
    }
    if (j < e) {
        int s0 = g_csr[j];
        float w0 = di * g_dinv[s0];
        float4 v0 = *(const float4*)&g_h[(size_t)s0 * C + lane * 4];
        acc.x += w0 * v0.x;
        acc.y += w0 * v0.y;
        acc.z += w0 * v0.z;
        acc.w += w0 * v0.w;
    }

    const float* scale = &g_aff[layer * 2 * C];
    const float* shift = &g_aff[layer * 2 * C + C];
    float4 sc = *(const float4*)&scale[lane * 4];
    float4 sf = *(const float4*)&shift[lane * 4];
    float4 r;
    r.x = fmaxf(acc.x * sc.x + sf.x, 0.f);
    r.y = fmaxf(acc.y * sc.y + sf.y, 0.f);
    r.z = fmaxf(acc.z * sc.z + sf.z, 0.f);
    r.w = fmaxf(acc.w * sc.w + sf.w, 0.f);
    *(float4*)&g_y[(size_t)w * C + lane * 4] = r;
}

// ---------------- layer 3: project to 2 channels then aggregate ----------------
__global__ void k_gemm3(const float* __restrict__ W3, int n) {
    __shared__ float w[256];
    if (threadIdx.x < 256) w[threadIdx.x] = W3[threadIdx.x];
    __syncthreads();
    int i = blockIdx.x * blockDim.x + threadIdx.x;
    if (i >= n) return;
    float a0 = 0.f, a1 = 0.f;
#pragma unroll
    for (int k = 0; k < C; k += 4) {
        float4 xv = *(const float4*)&g_y[(size_t)i * C + k];
        a0 += xv.x * w[2 * k + 0] + xv.y * w[2 * k + 2] + xv.z * w[2 * k + 4] + xv.w * w[2 * k + 6];
        a1 += xv.x * w[2 * k + 1] + xv.y * w[2 * k + 3] + xv.z * w[2 * k + 5] + xv.w * w[2 * k + 7];
    }
    *(float2*)&g_z[(size_t)i * 2] = make_float2(a0, a1);
}

__global__ void k_spmm3(const float* __restrict__ b3, float* __restrict__ out, int n) {
    int w = (blockIdx.x * blockDim.x + threadIdx.x) >> 5;
    if (w >= n) return;
    int lane = threadIdx.x & 31;
    float di = g_dinv[w];
    float a0 = 0.f, a1 = 0.f;
    int s = g_off[w], e = g_off[w + 1];
    for (int j = s + lane; j < e; j += 32) {
        int src = g_csr[j];
        float wt = di * g_dinv[src];
        float2 zv = *(const float2*)&g_z[(size_t)src * 2];
        a0 += wt * zv.x;
        a1 += wt * zv.y;
    }
#pragma unroll
    for (int o = 16; o > 0; o >>= 1) {
        a0 += __shfl_down_sync(0xFFFFFFFFu, a0, o);
        a1 += __shfl_down_sync(0xFFFFFFFFu, a1, o);
    }
    if (lane == 0) {
        float2 zv = *(const float2*)&g_z[(size_t)w * 2];
        float sw = di * di;
        out[(size_t)w * 2 + 0] = a0 + sw * zv.x + b3[0];
        out[(size_t)w * 2 + 1] = a1 + sw * zv.y + b3[1];
    }
}

// ---------------- launch ----------------
extern "C" void kernel_launch(void* const* d_in, const int* in_sizes, int n_in,
                              void* d_out, int out_size) {
    const float* x  = (const float*)d_in[0];
    const int*   ei = (const int*)d_in[1];
    const float* W1 = (const float*)d_in[2];
    const float* b1 = (const float*)d_in[3];
    const float* g1 = (const float*)d_in[4];
    const float* be1 = (const float*)d_in[5];
    const float* rm1 = (const float*)d_in[6];
    const float* rv1 = (const float*)d_in[7];
    const float* W2 = (const float*)d_in[8];
    const float* b2 = (const float*)d_in[9];
    const float* g2 = (const float*)d_in[10];
    const float* be2 = (const float*)d_in[11];
    const float* rm2 = (const float*)d_in[12];
    const float* rv2 = (const float*)d_in[13];
    const float* W3 = (const float*)d_in[14];
    const float* b3 = (const float*)d_in[15];
    float* out = (float*)d_out;

    int n = in_sizes[0] / C;       // 100000
    int e = in_sizes[1] / 2;       // 1600000
    const int* src = ei;
    const int* dst = ei + e;

    int nb_n = (n + 255) / 256;
    int nb_e = (e + 255) / 256;
    int nb_scan = (n + 1023) / 1024;
    int nb_gemm = (n + 63) / 64;
    int nb_warp = (n * 32 + 255) / 256;   // warp-per-row kernels

    // CSR + norm build
    k_zero_cnt<<<nb_n, 256>>>(n);
    k_hist<<<nb_e, 256>>>(dst, e);
    k_scan1<<<nb_scan, 1024>>>(n);
    k_scan2<<<1, 128>>>(nb_scan);
    k_scan3<<<nb_n, 256>>>(n, e);
    k_fill<<<nb_e, 256>>>(src, dst, e);

    // fold bias+BN
    k_affine<<<1, 128>>>(b1, g1, be1, rm1, rv1, 0);
    k_affine<<<1, 128>>>(b2, g2, be2, rm2, rv2, 1);

    // layer 1
    k_gemm128<<<nb_gemm, 256>>>(x, 1, W1, n);
    k_spmm<<<nb_warp, 256>>>(0, n);
    // layer 2
    k_gemm128<<<nb_gemm, 256>>>(nullptr, 0, W2, n);
    k_spmm<<<nb_warp, 256>>>(1, n);
    // layer 3
    k_gemm3<<<nb_n, 256>>>(W3, n);
    k_spmm3<<<nb_warp, 256>>>(b3, out, n);
}

// round 2
// speedup vs baseline: 1.0028x; 1.0028x over previous
#include <cuda_runtime.h>
#include <cuda_bf16.h>
#include <cstdint>

// Problem constants (fixed by the dataset)
#define MAXN 100000
#define MAXE 1600000
#define C 128
#define EPS_BN 1e-5f

// ---------------- persistent device scratch (no allocs allowed) ----------------
__device__ int   g_cnt[MAXN];
__device__ int   g_off[MAXN + 1];
__device__ int   g_cur[MAXN];
__device__ int   g_csr[MAXE];
__device__ float g_dinv[MAXN];
__device__ int   g_bsum[256];
__device__ float g_h[(size_t)MAXN * C];   // GEMM output buffer
__device__ float g_y[(size_t)MAXN * C];   // SpMM output buffer
__device__ float g_z[(size_t)MAXN * 2];   // layer-3 projected features
__device__ float g_aff[2 * 2 * C];        // [layer][scale|shift][C]

// ---------------- preprocessing ----------------
__global__ void k_zero_cnt(int n) {
    int i = blockIdx.x * blockDim.x + threadIdx.x;
    if (i < n) g_cnt[i] = 0;
}

__global__ void k_hist(const int* __restrict__ dst, int e) {
    int i = blockIdx.x * blockDim.x + threadIdx.x;
    if (i < e) atomicAdd(&g_cnt[dst[i]], 1);
}

// block-level exclusive scan, 1024 elems/block
__global__ void k_scan1(int n) {
    __shared__ int sh[1024];
    int i = blockIdx.x * 1024 + threadIdx.x;
    int v = (i < n) ? g_cnt[i] : 0;
    sh[threadIdx.x] = v;
    __syncthreads();
    for (int d = 1; d < 1024; d <<= 1) {
        int t = (threadIdx.x >= (unsigned)d) ? sh[threadIdx.x - d] : 0;
        __syncthreads();
        sh[threadIdx.x] += t;
        __syncthreads();
    }
    if (i < n) g_off[i] = sh[threadIdx.x] - v;     // exclusive
    if (threadIdx.x == 1023) g_bsum[blockIdx.x] = sh[1023];
}

// scan of block sums (nb <= 128)
__global__ void k_scan2(int nb) {
    __shared__ int sh[128];
    int t = threadIdx.x;
    int v = (t < nb) ? g_bsum[t] : 0;
    sh[t] = v;
    __syncthreads();
    for (int d = 1; d < 128; d <<= 1) {
        int u = (t >= d) ? sh[t - d] : 0;
        __syncthreads();
        sh[t] += u;
        __syncthreads();
    }
    if (t < nb) g_bsum[t] = sh[t] - v;             // exclusive
}

__global__ void k_scan3(int n, int e) {
    int i = blockIdx.x * blockDim.x + threadIdx.x;
    if (i < n) {
        int o = g_off[i] + g_bsum[i >> 10];
        g_off[i] = o;
        g_cur[i] = o;
        g_dinv[i] = rsqrtf((float)(g_cnt[i] + 1));  // +1 self loop
    }
    if (i == 0) g_off[n] = e;
}

__global__ void k_fill(const int* __restrict__ src, const int* __restrict__ dst, int e) {
    int i = blockIdx.x * blockDim.x + threadIdx.x;
    if (i < e) {
        int p = atomicAdd(&g_cur[dst[i]], 1);
        g_csr[p] = src[i];
    }
}

// fold bias + BN(eval) into per-channel scale/shift
__global__ void k_affine(const float* __restrict__ b, const float* __restrict__ g,
                         const float* __restrict__ be, const float* __restrict__ rm,
                         const float* __restrict__ rv, int layer) {
    int c = threadIdx.x;
    if (c < C) {
        float s = g[c] * rsqrtf(rv[c] + EPS_BN);
        g_aff[layer * 2 * C + c] = s;                       // scale
        g_aff[layer * 2 * C + C + c] = (b[c] - rm[c]) * s + be[c];  // shift
    }
}

// ---------------- dense GEMM: O[n x 128] = A[n x 128] @ W[128 x 128] ----------------
// Block tile 64x128, 256 threads, thread tile 8x4. Output -> g_h.
__global__ void k_gemm128(const float* __restrict__ Aext, int useExt,
                          const float* __restrict__ W, int n) {
    __shared__ float xs[64][16];
    __shared__ float ws[16][128];
    const float* A = useExt ? Aext : g_y;
    int tid = threadIdx.x;
    int tc = tid & 31;          // col group (4 cols)
    int tr = tid >> 5;          // row group (8 rows)
    int bm0 = blockIdx.x * 64;

    float4 acc[8];
#pragma unroll
    for (int i = 0; i < 8; i++) acc[i] = make_float4(0.f, 0.f, 0.f, 0.f);

    int xrow = tid >> 2;        // 0..63
    int xk = (tid & 3) * 4;     // 0,4,8,12

    for (int k0 = 0; k0 < 128; k0 += 16) {
        float4 xv4 = make_float4(0.f, 0.f, 0.f, 0.f);
        if (bm0 + xrow < n)
            xv4 = *(const float4*)&A[(size_t)(bm0 + xrow) * C + k0 + xk];
        *(float4*)&xs[xrow][xk] = xv4;
#pragma unroll
        for (int q = 0; q < 2; q++) {
            int lin = tid * 2 + q;          // 0..511 (float4 index)
            int wr = lin >> 5;              // 0..15
            int wc = (lin & 31) * 4;        // 0..124
            *(float4*)&ws[wr][wc] = *(const float4*)&W[(size_t)(k0 + wr) * C + wc];
        }
        __syncthreads();
#pragma unroll
        for (int kk = 0; kk < 16; kk++) {
            float4 wv = *(const float4*)&ws[kk][tc * 4];
#pragma unroll
            for (int i = 0; i < 8; i++) {
                float xv = xs[tr * 8 + i][kk];
                acc[i].x += xv * wv.x;
                acc[i].y += xv * wv.y;
                acc[i].z += xv * wv.z;
                acc[i].w += xv * wv.w;
            }
        }
        __syncthreads();
    }
#pragma unroll
    for (int i = 0; i < 8; i++) {
        int r = bm0 + tr * 8 + i;
        if (r < n) *(float4*)&g_h[(size_t)r * C + tc * 4] = acc[i];
    }
}

// ---------------- SpMM: one warp per dst row, 128 channels in float4 regs ----------------
// reads g_h, writes g_y. Epilogue: y = relu(acc*scale + shift)
__global__ void k_spmm(int layer, int n) {
    int w = (blockIdx.x * blockDim.x + threadIdx.x) >> 5;
    if (w >= n) return;
    int lane = threadIdx.x & 31;
    float di = g_dinv[w];

    // self loop: weight dinv^2
    float4 hv = *(const float4*)&g_h[(size_t)w * C + lane * 4];
    float sw = di * di;
    float4 acc = make_float4(sw * hv.x, sw * hv.y, sw * hv.z, sw * hv.w);

    int s = g_off[w], e = g_off[w + 1];
    int j = s;
    for (; j + 1 < e; j += 2) {
        int s0 = g_csr[j], s1 = g_csr[j + 1];
        float w0 = di * g_dinv[s0];
        float w1 = di * g_dinv[s1];
        float4 v0 = *(const float4*)&g_h[(size_t)s0 * C + lane * 4];
        float4 v1 = *(const float4*)&g_h[(size_t)s1 * C + lane * 4];
        acc.x += w0 * v0.x + w1 * v1.x;
        acc.y += w0 * v0.y + w1 * v1.y;
        acc.z += w0 * v0.z + w1 * v1.z;
        acc.w += w0 * v0.w + w1 * v1.w;
    }
    if (j < e) {
        int s0 = g_csr[j];
        float w0 = di * g_dinv[s0];
        float4 v0 = *(const float4*)&g_h[(size_t)s0 * C + lane * 4];
        acc.x += w0 * v0.x;
        acc.y += w0 * v0.y;
        acc.z += w0 * v0.z;
        acc.w += w0 * v0.w;
    }

    const float* scale = &g_aff[layer * 2 * C];
    const float* shift = &g_aff[layer * 2 * C + C];
    float4 sc = *(const float4*)&scale[lane * 4];
    float4 sf = *(const float4*)&shift[lane * 4];
    float4 r;
    r.x = fmaxf(acc.x * sc.x + sf.x, 0.f);
    r.y = fmaxf(acc.y * sc.y + sf.y, 0.f);
    r.z = fmaxf(acc.z * sc.z + sf.z, 0.f);
    r.w = fmaxf(acc.w * sc.w + sf.w, 0.f);
    *(float4*)&g_y[(size_t)w * C + lane * 4] = r;
}

// ---------------- layer 3: project to 2 channels then aggregate ----------------
__global__ void k_gemm3(const float* __restrict__ W3, int n) {
    __shared__ float w[256];
    if (threadIdx.x < 256) w[threadIdx.x] = W3[threadIdx.x];
    __syncthreads();
    int i = blockIdx.x * blockDim.x + threadIdx.x;
    if (i >= n) return;
    float a0 = 0.f, a1 = 0.f;
#pragma unroll
    for (int k = 0; k < C; k += 4) {
        float4 xv = *(const float4*)&g_y[(size_t)i * C + k];
        a0 += xv.x * w[2 * k + 0] + xv.y * w[2 * k + 2] + xv.z * w[2 * k + 4] + xv.w * w[2 * k + 6];
        a1 += xv.x * w[2 * k + 1] + xv.y * w[2 * k + 3] + xv.z * w[2 * k + 5] + xv.w * w[2 * k + 7];
    }
    *(float2*)&g_z[(size_t)i * 2] = make_float2(a0, a1);
}

__global__ void k_spmm3(const float* __restrict__ b3, float* __restrict__ out, int n) {
    int w = (blockIdx.x * blockDim.x + threadIdx.x) >> 5;
    if (w >= n) return;
    int lane = threadIdx.x & 31;
    float di = g_dinv[w];
    float a0 = 0.f, a1 = 0.f;
    int s = g_off[w], e = g_off[w + 1];
    for (int j = s + lane; j < e; j += 32) {
        int src = g_csr[j];
        float wt = di * g_dinv[src];
        float2 zv = *(const float2*)&g_z[(size_t)src * 2];
        a0 += wt * zv.x;
        a1 += wt * zv.y;
    }
#pragma unroll
    for (int o = 16; o > 0; o >>= 1) {
        a0 += __shfl_down_sync(0xFFFFFFFFu, a0, o);
        a1 += __shfl_down_sync(0xFFFFFFFFu, a1, o);
    }
    if (lane == 0) {
        float2 zv = *(const float2*)&g_z[(size_t)w * 2];
        float sw = di * di;
        out[(size_t)w * 2 + 0] = a0 + sw * zv.x + b3[0];
        out[(size_t)w * 2 + 1] = a1 + sw * zv.y + b3[1];
    }
}

// ---------------- launch ----------------
extern "C" void kernel_launch(void* const* d_in, const int* in_sizes, int n_in,
                              void* d_out, int out_size) {
    const float* x  = (const float*)d_in[0];
    const int*   ei = (const int*)d_in[1];
    const float* W1 = (const float*)d_in[2];
    const float* b1 = (const float*)d_in[3];
    const float* g1 = (const float*)d_in[4];
    const float* be1 = (const float*)d_in[5];
    const float* rm1 = (const float*)d_in[6];
    const float* rv1 = (const float*)d_in[7];
    const float* W2 = (const float*)d_in[8];
    const float* b2 = (const float*)d_in[9];
    const float* g2 = (const float*)d_in[10];
    const float* be2 = (const float*)d_in[11];
    const float* rm2 = (const float*)d_in[12];
    const float* rv2 = (const float*)d_in[13];
    const float* W3 = (const float*)d_in[14];
    const float* b3 = (const float*)d_in[15];
    float* out = (float*)d_out;

    int n = in_sizes[0] / C;       // 100000
    int e = in_sizes[1] / 2;       // 1600000
    const int* src = ei;
    const int* dst = ei + e;

    int nb_n = (n + 255) / 256;
    int nb_e = (e + 255) / 256;
    int nb_scan = (n + 1023) / 1024;
    int nb_gemm = (n + 63) / 64;
    int nb_warp = (n * 32 + 255) / 256;   // warp-per-row kernels

    // CSR + norm build
    k_zero_cnt<<<nb_n, 256>>>(n);
    k_hist<<<nb_e, 256>>>(dst, e);
    k_scan1<<<nb_scan, 1024>>>(n);
    k_scan2<<<1, 128>>>(nb_scan);
    k_scan3<<<nb_n, 256>>>(n, e);
    k_fill<<<nb_e, 256>>>(src, dst, e);

    // fold bias+BN
    k_affine<<<1, 128>>>(b1, g1, be1, rm1, rv1, 0);
    k_affine<<<1, 128>>>(b2, g2, be2, rm2, rv2, 1);

    // layer 1
    k_gemm128<<<nb_gemm, 256>>>(x, 1, W1, n);
    k_spmm<<<nb_warp, 256>>>(0, n);
    // layer 2
    k_gemm128<<<nb_gemm, 256>>>(nullptr, 0, W2, n);
    k_spmm<<<nb_warp, 256>>>(1, n);
    // layer 3
    k_gemm3<<<nb_n, 256>>>(W3, n);
    k_spmm3<<<nb_warp, 256>>>(b3, out, n);
}

// round 3
// speedup vs baseline: 1.0037x; 1.0009x over previous
#include <cuda_runtime.h>
#include <cuda_bf16.h>
#include <cstdint>

// Problem constants (fixed by the dataset)
#define MAXN 100000
#define MAXE 1600000
#define C 128
#define EPS_BN 1e-5f

// ---------------- persistent device scratch (no allocs allowed) ----------------
__device__ int   g_cnt[MAXN];
__device__ int   g_off[MAXN + 1];
__device__ int   g_cur[MAXN];
__device__ int   g_csr[MAXE];
__device__ float g_dinv[MAXN];
__device__ int   g_bsum[256];
__device__ float g_h[(size_t)MAXN * C];   // GEMM output buffer
__device__ float g_y[(size_t)MAXN * C];   // SpMM output buffer
__device__ float g_z[(size_t)MAXN * 2];   // layer-3 projected features
__device__ float g_aff[2 * 2 * C];        // [layer][scale|shift][C]

// ---------------- preprocessing ----------------
__global__ void k_zero_cnt(int n) {
    int i = blockIdx.x * blockDim.x + threadIdx.x;
    if (i < n) g_cnt[i] = 0;
}

__global__ void k_hist(const int* __restrict__ dst, int e) {
    int i = blockIdx.x * blockDim.x + threadIdx.x;
    if (i < e) atomicAdd(&g_cnt[dst[i]], 1);
}

// block-level exclusive scan, 1024 elems/block
__global__ void k_scan1(int n) {
    __shared__ int sh[1024];
    int i = blockIdx.x * 1024 + threadIdx.x;
    int v = (i < n) ? g_cnt[i] : 0;
    sh[threadIdx.x] = v;
    __syncthreads();
    for (int d = 1; d < 1024; d <<= 1) {
        int t = (threadIdx.x >= (unsigned)d) ? sh[threadIdx.x - d] : 0;
        __syncthreads();
        sh[threadIdx.x] += t;
        __syncthreads();
    }
    if (i < n) g_off[i] = sh[threadIdx.x] - v;     // exclusive
    if (threadIdx.x == 1023) g_bsum[blockIdx.x] = sh[1023];
}

// scan of block sums (nb <= 128)
__global__ void k_scan2(int nb) {
    __shared__ int sh[128];
    int t = threadIdx.x;
    int v = (t < nb) ? g_bsum[t] : 0;
    sh[t] = v;
    __syncthreads();
    for (int d = 1; d < 128; d <<= 1) {
        int u = (t >= d) ? sh[t - d] : 0;
        __syncthreads();
        sh[t] += u;
        __syncthreads();
    }
    if (t < nb) g_bsum[t] = sh[t] - v;             // exclusive
}

__global__ void k_scan3(int n, int e) {
    int i = blockIdx.x * blockDim.x + threadIdx.x;
    if (i < n) {
        int o = g_off[i] + g_bsum[i >> 10];
        g_off[i] = o;
        g_cur[i] = o;
        g_dinv[i] = rsqrtf((float)(g_cnt[i] + 1));  // +1 self loop
    }
    if (i == 0) g_off[n] = e;
}

__global__ void k_fill(const int* __restrict__ src, const int* __restrict__ dst, int e) {
    int i = blockIdx.x * blockDim.x + threadIdx.x;
    if (i < e) {
        int p = atomicAdd(&g_cur[dst[i]], 1);
        g_csr[p] = src[i];
    }
}

// fold bias + BN(eval) into per-channel scale/shift
__global__ void k_affine(const float* __restrict__ b, const float* __restrict__ g,
                         const float* __restrict__ be, const float* __restrict__ rm,
                         const float* __restrict__ rv, int layer) {
    int c = threadIdx.x;
    if (c < C) {
        float s = g[c] * rsqrtf(rv[c] + EPS_BN);
        g_aff[layer * 2 * C + c] = s;                       // scale
        g_aff[layer * 2 * C + C + c] = (b[c] - rm[c]) * s + be[c];  // shift
    }
}

// ---------------- dense GEMM: O[n x 128] = A[n x 128] @ W[128 x 128] ----------------
// Block tile 64x128, 256 threads, thread tile 8x4. Output -> g_h.
__global__ void k_gemm128(const float* __restrict__ Aext, int useExt,
                          const float* __restrict__ W, int n) {
    __shared__ float xs[64][16];
    __shared__ float ws[16][128];
    const float* A = useExt ? Aext : g_y;
    int tid = threadIdx.x;
    int tc = tid & 31;          // col group (4 cols)
    int tr = tid >> 5;          // row group (8 rows)
    int bm0 = blockIdx.x * 64;

    float4 acc[8];
#pragma unroll
    for (int i = 0; i < 8; i++) acc[i] = make_float4(0.f, 0.f, 0.f, 0.f);

    int xrow = tid >> 2;        // 0..63
    int xk = (tid & 3) * 4;     // 0,4,8,12

    for (int k0 = 0; k0 < 128; k0 += 16) {
        float4 xv4 = make_float4(0.f, 0.f, 0.f, 0.f);
        if (bm0 + xrow < n)
            xv4 = *(const float4*)&A[(size_t)(bm0 + xrow) * C + k0 + xk];
        *(float4*)&xs[xrow][xk] = xv4;
#pragma unroll
        for (int q = 0; q < 2; q++) {
            int lin = tid * 2 + q;          // 0..511 (float4 index)
            int wr = lin >> 5;              // 0..15
            int wc = (lin & 31) * 4;        // 0..124
            *(float4*)&ws[wr][wc] = *(const float4*)&W[(size_t)(k0 + wr) * C + wc];
        }
        __syncthreads();
#pragma unroll
        for (int kk = 0; kk < 16; kk++) {
            float4 wv = *(const float4*)&ws[kk][tc * 4];
#pragma unroll
            for (int i = 0; i < 8; i++) {
                float xv = xs[tr * 8 + i][kk];
                acc[i].x += xv * wv.x;
                acc[i].y += xv * wv.y;
                acc[i].z += xv * wv.z;
                acc[i].w += xv * wv.w;
            }
        }
        __syncthreads();
    }
#pragma unroll
    for (int i = 0; i < 8; i++) {
        int r = bm0 + tr * 8 + i;
        if (r < n) *(float4*)&g_h[(size_t)r * C + tc * 4] = acc[i];
    }
}

// ---------------- SpMM: one warp per dst row, 128 channels in float4 regs ----------------
// reads g_h, writes g_y. Epilogue: y = relu(acc*scale + shift)
__global__ void k_spmm(int layer, int n) {
    int w = (blockIdx.x * blockDim.x + threadIdx.x) >> 5;
    if (w >= n) return;
    int lane = threadIdx.x & 31;
    float di = g_dinv[w];

    // self loop: weight dinv^2
    float4 hv = *(const float4*)&g_h[(size_t)w * C + lane * 4];
    float sw = di * di;
    float4 acc = make_float4(sw * hv.x, sw * hv.y, sw * hv.z, sw * hv.w);

    int s = g_off[w], e = g_off[w + 1];
    int j = s;
    for (; j + 1 < e; j += 2) {
        int s0 = g_csr[j], s1 = g_csr[j + 1];
        float w0 = di * g_dinv[s0];
        float w1 = di * g_dinv[s1];
        float4 v0 = *(const float4*)&g_h[(size_t)s0 * C + lane * 4];
        float4 v1 = *(const float4*)&g_h[(size_t)s1 * C + lane * 4];
        acc.x += w0 * v0.x + w1 * v1.x;
        acc.y += w0 * v0.y + w1 * v1.y;
        acc.z += w0 * v0.z + w1 * v1.z;
        acc.w += w0 * v0.w + w1 * v1.w;
    }
    if (j < e) {
        int s0 = g_csr[j];
        float w0 = di * g_dinv[s0];
        float4 v0 = *(const float4*)&g_h[(size_t)s0 * C + lane * 4];
        acc.x += w0 * v0.x;
        acc.y += w0 * v0.y;
        acc.z += w0 * v0.z;
        acc.w += w0 * v0.w;
    }

    const float* scale = &g_aff[layer * 2 * C];
    const float* shift = &g_aff[layer * 2 * C + C];
    float4 sc = *(const float4*)&scale[lane * 4];
    float4 sf = *(const float4*)&shift[lane * 4];
    float4 r;
    r.x = fmaxf(acc.x * sc.x + sf.x, 0.f);
    r.y = fmaxf(acc.y * sc.y + sf.y, 0.f);
    r.z = fmaxf(acc.z * sc.z + sf.z, 0.f);
    r.w = fmaxf(acc.w * sc.w + sf.w, 0.f);
    *(float4*)&g_y[(size_t)w * C + lane * 4] = r;
}

// ---------------- layer 3: project to 2 channels then aggregate ----------------
__global__ void k_gemm3(const float* __restrict__ W3, int n) {
    __shared__ float w[256];
    if (threadIdx.x < 256) w[threadIdx.x] = W3[threadIdx.x];
    __syncthreads();
    int i = blockIdx.x * blockDim.x + threadIdx.x;
    if (i >= n) return;
    float a0 = 0.f, a1 = 0.f;
#pragma unroll
    for (int k = 0; k < C; k += 4) {
        float4 xv = *(const float4*)&g_y[(size_t)i * C + k];
        a0 += xv.x * w[2 * k + 0] + xv.y * w[2 * k + 2] + xv.z * w[2 * k + 4] + xv.w * w[2 * k + 6];
        a1 += xv.x * w[2 * k + 1] + xv.y * w[2 * k + 3] + xv.z * w[2 * k + 5] + xv.w * w[2 * k + 7];
    }
    *(float2*)&g_z[(size_t)i * 2] = make_float2(a0, a1);
}

__global__ void k_spmm3(const float* __restrict__ b3, float* __restrict__ out, int n) {
    int w = (blockIdx.x * blockDim.x + threadIdx.x) >> 5;
    if (w >= n) return;
    int lane = threadIdx.x & 31;
    float di = g_dinv[w];
    float a0 = 0.f, a1 = 0.f;
    int s = g_off[w], e = g_off[w + 1];
    for (int j = s + lane; j < e; j += 32) {
        int src = g_csr[j];
        float wt = di * g_dinv[src];
        float2 zv = *(const float2*)&g_z[(size_t)src * 2];
        a0 += wt * zv.x;
        a1 += wt * zv.y;
    }
#pragma unroll
    for (int o = 16; o > 0; o >>= 1) {
        a0 += __shfl_down_sync(0xFFFFFFFFu, a0, o);
        a1 += __shfl_down_sync(0xFFFFFFFFu, a1, o);
    }
    if (lane == 0) {
        float2 zv = *(const float2*)&g_z[(size_t)w * 2];
        float sw = di * di;
        out[(size_t)w * 2 + 0] = a0 + sw * zv.x + b3[0];
        out[(size_t)w * 2 + 1] = a1 + sw * zv.y + b3[1];
    }
}

// ---------------- launch ----------------
extern "C" void kernel_launch(void* const* d_in, const int* in_sizes, int n_in,
                              void* d_out, int out_size) {
    const float* x  = (const float*)d_in[0];
    const int*   ei = (const int*)d_in[1];
    const float* W1 = (const float*)d_in[2];
    const float* b1 = (const float*)d_in[3];
    const float* g1 = (const float*)d_in[4];
    const float* be1 = (const float*)d_in[5];
    const float* rm1 = (const float*)d_in[6];
    const float* rv1 = (const float*)d_in[7];
    const float* W2 = (const float*)d_in[8];
    const float* b2 = (const float*)d_in[9];
    const float* g2 = (const float*)d_in[10];
    const float* be2 = (const float*)d_in[11];
    const float* rm2 = (const float*)d_in[12];
    const float* rv2 = (const float*)d_in[13];
    const float* W3 = (const float*)d_in[14];
    const float* b3 = (const float*)d_in[15];
    float* out = (float*)d_out;

    int n = in_sizes[0] / C;       // 100000
    int e = in_sizes[1] / 2;       // 1600000
    const int* src = ei;
    const int* dst = ei + e;

    int nb_n = (n + 255) / 256;
    int nb_e = (e + 255) / 256;
    int nb_scan = (n + 1023) / 1024;
    int nb_gemm = (n + 63) / 64;
    int nb_warp = (n * 32 + 255) / 256;   // warp-per-row kernels

    // CSR + norm build
    k_zero_cnt<<<nb_n, 256>>>(n);
    k_hist<<<nb_e, 256>>>(dst, e);
    k_scan1<<<nb_scan, 1024>>>(n);
    k_scan2<<<1, 128>>>(nb_scan);
    k_scan3<<<nb_n, 256>>>(n, e);
    k_fill<<<nb_e, 256>>>(src, dst, e);

    // fold bias+BN
    k_affine<<<1, 128>>>(b1, g1, be1, rm1, rv1, 0);
    k_affine<<<1, 128>>>(b2, g2, be2, rm2, rv2, 1);

    // layer 1
    k_gemm128<<<nb_gemm, 256>>>(x, 1, W1, n);
    k_spmm<<<nb_warp, 256>>>(0, n);
    // layer 2
    k_gemm128<<<nb_gemm, 256>>>(nullptr, 0, W2, n);
    k_spmm<<<nb_warp, 256>>>(1, n);
    // layer 3
    k_gemm3<<<nb_n, 256>>>(W3, n);
    k_spmm3<<<nb_warp, 256>>>(b3, out, n);
}